// round 1
// baseline (speedup 1.0000x reference)
#include <cuda_runtime.h>

#define Tn 512
#define Bn 2
#define Hn 128
#define En 32
#define Vn 32000

// ---------------- scratch (no allocations allowed) ----------------
__device__ float g_xp[Bn * Tn * Hn];    // input projections + biases
__device__ float g_rnn[Bn * Tn * Hn];   // RNN outputs
__device__ float g_q[Bn * Tn * Hn];     // query = rnn @ W1^T
__device__ float g_k[Bn * Tn * Hn];     // keys  = rnn @ W2^T
__device__ float g_proj[Bn * Tn * Hn];  // relu([rnn,ctx] @ Wp^T + bp)
__device__ int g_is64;                  // x element width flag

// accurate-enough fast tanh: ~1e-6 rel err (2 MUFU + few FMA)
__device__ __forceinline__ float fast_tanh(float x) {
    x = fminf(fmaxf(x, -15.f), 15.f);
    float e = __expf(2.f * x);
    return __fdividef(e - 1.f, e + 1.f);
}

// ---------------- K0: detect int64 vs int32 token layout ----------------
__global__ void k_detect(const unsigned* __restrict__ xw) {
    __shared__ int nz;
    if (threadIdx.x == 0) nz = 0;
    __syncthreads();
    // If int64 layout, words 2i+1 are high words of values in [0,32000) -> all 0.
    // If int32 layout, words 2i+1 are 512 random token ids -> some nonzero.
    for (int i = threadIdx.x; i < 512; i += blockDim.x)
        if (xw[2 * i + 1]) atomicOr(&nz, 1);
    __syncthreads();
    if (threadIdx.x == 0) g_is64 = (nz == 0);
}

// ---------------- K1: embedding + input projection ----------------
// xp[b,t,h] = dot(embed_table[x[b,t]], W_ih[h,:]) + b_ih[h] + b_hh[h]
__global__ void k_embed(const void* __restrict__ xraw,
                        const float* __restrict__ etab,
                        const float* __restrict__ W_ih,
                        const float* __restrict__ b_ih,
                        const float* __restrict__ b_hh) {
    int bt = blockIdx.x;
    int h = threadIdx.x;
    __shared__ float emb[En];
    __shared__ int sidx;
    if (threadIdx.x == 0) {
        long long idx;
        if (g_is64) idx = ((const long long*)xraw)[bt];
        else        idx = (long long)(((const int*)xraw)[bt]);
        sidx = (int)idx;
    }
    __syncthreads();
    if (h < En) emb[h] = etab[(long long)sidx * En + h];
    __syncthreads();
    float acc = b_ih[h] + b_hh[h];
#pragma unroll
    for (int e = 0; e < En; e++) acc = fmaf(emb[e], W_ih[h * En + e], acc);
    g_xp[bt * Hn + h] = acc;
}

// ---------------- K2: sequential tanh-RNN scan ----------------
// One block per batch; 256 threads; thread pair (j, half) owns output j,
// half of the K-range of W_hh row j cached in registers.
__global__ void k_rnn(const float* __restrict__ hidden,
                      const float* __restrict__ W_hh,
                      float* __restrict__ out_hidden) {
    int b = blockIdx.x;
    int tid = threadIdx.x;
    int j = tid >> 1, half = tid & 1;
    float w[64];
#pragma unroll
    for (int kk = 0; kk < 64; kk++) w[kk] = W_hh[j * Hn + half * 64 + kk];
    __shared__ float hbuf[2][Hn];
    if (tid < Hn) hbuf[0][tid] = hidden[b * Hn + tid];
    __syncthreads();
    const float* xp = g_xp + b * Tn * Hn;
    float* rnn = g_rnn + b * Tn * Hn;
    for (int t = 0; t < Tn; t++) {
        const float4* h4 = (const float4*)(&hbuf[t & 1][half * 64]);
        float acc = 0.f;
#pragma unroll
        for (int q = 0; q < 16; q++) {
            float4 hv = h4[q];
            acc = fmaf(w[q * 4 + 0], hv.x, acc);
            acc = fmaf(w[q * 4 + 1], hv.y, acc);
            acc = fmaf(w[q * 4 + 2], hv.z, acc);
            acc = fmaf(w[q * 4 + 3], hv.w, acc);
        }
        acc += __shfl_xor_sync(0xffffffffu, acc, 1);
        if (half == 0) {
            float hn = fast_tanh(xp[t * Hn + j] + acc);
            hbuf[(t + 1) & 1][j] = hn;
            rnn[t * Hn + j] = hn;
            if (t == Tn - 1) out_hidden[b * Hn + j] = hn;
        }
        __syncthreads();
    }
}

// ---------------- K3: q/k projections ----------------
__global__ void k_qk(const float* __restrict__ W1, const float* __restrict__ W2) {
    int bt = blockIdx.x;
    int tid = threadIdx.x;
    __shared__ float r[Hn];
    if (tid < Hn) r[tid] = g_rnn[bt * Hn + tid];
    __syncthreads();
    int j = tid & 127;
    const float* W = (tid < 128) ? W1 : W2;
    float* dst = (tid < 128) ? g_q : g_k;
    const float4* w4 = (const float4*)(W + j * Hn);
    const float4* r4 = (const float4*)r;
    float acc = 0.f;
#pragma unroll
    for (int q = 0; q < 32; q++) {
        float4 wv = w4[q];
        float4 rv = r4[q];
        acc = fmaf(wv.x, rv.x, acc);
        acc = fmaf(wv.y, rv.y, acc);
        acc = fmaf(wv.z, rv.z, acc);
        acc = fmaf(wv.w, rv.w, acc);
    }
    dst[bt * Hn + j] = acc;
}

// ---------------- K4: additive attention + softmax + context + Wp proj ----------------
__global__ void k_attn(const float* __restrict__ v,
                       const float* __restrict__ Wp,
                       const float* __restrict__ bp,
                       float* __restrict__ out_w) {
    int bt = blockIdx.x;
    int b = bt >> 9, t = bt & 511;
    int tid = threadIdx.x;
    __shared__ float q_s[Hn], v_s[Hn], r_s[Hn], ctx_s[Hn];
    __shared__ float sc[Tn];
    __shared__ float red[256];
    if (tid < Hn) {
        q_s[tid] = g_q[bt * Hn + tid];
        v_s[tid] = v[tid];
        r_s[tid] = g_rnn[bt * Hn + tid];
    }
    __syncthreads();

    // scores[s] = sum_h tanh(q[t,h] + k[s,h]) * v[h],  s <= t
    int warp = tid >> 5, lane = tid & 31;
    for (int s = warp; s <= t; s += 8) {
        const float* krow = g_k + (b * Tn + s) * Hn;
        float p = 0.f;
#pragma unroll
        for (int i = 0; i < 4; i++) {
            int h = i * 32 + lane;
            p = fmaf(fast_tanh(q_s[h] + krow[h]), v_s[h], p);
        }
#pragma unroll
        for (int off = 16; off; off >>= 1) p += __shfl_xor_sync(0xffffffffu, p, off);
        if (lane == 0) sc[s] = p;
    }
    __syncthreads();

    // softmax over [0, t]
    float m = -1e30f;
    for (int s = tid; s <= t; s += 256) m = fmaxf(m, sc[s]);
    red[tid] = m;
    __syncthreads();
    for (int st = 128; st; st >>= 1) {
        if (tid < st) red[tid] = fmaxf(red[tid], red[tid + st]);
        __syncthreads();
    }
    float mx = red[0];
    __syncthreads();
    float ssum = 0.f;
    for (int s = tid; s <= t; s += 256) {
        float e = __expf(sc[s] - mx);
        sc[s] = e;
        ssum += e;
    }
    red[tid] = ssum;
    __syncthreads();
    for (int st = 128; st; st >>= 1) {
        if (tid < st) red[tid] += red[tid + st];
        __syncthreads();
    }
    float rinv = __fdividef(1.f, red[0]);
    __syncthreads();
    for (int s = tid; s < Tn; s += 256) {
        float wv = (s <= t) ? sc[s] * rinv : 0.f;
        out_w[(size_t)bt * Tn + s] = wv;
        if (s <= t) sc[s] = wv;
    }
    __syncthreads();

    // context[h] = sum_s w[s] * rnn[b,s,h]
    {
        int h = tid & 127, part = tid >> 7;
        float c = 0.f;
        for (int s = part; s <= t; s += 2)
            c = fmaf(sc[s], g_rnn[(b * Tn + s) * Hn + h], c);
        red[tid] = c;
        __syncthreads();
        if (tid < Hn) ctx_s[tid] = red[tid] + red[tid + 128];
        __syncthreads();
    }

    // proj: relu([rnn, ctx] @ Wp^T + bp)
    {
        int j = tid >> 1, half = tid & 1;
        const float* src = half ? ctx_s : r_s;
        const float* wrow = Wp + j * (2 * Hn) + half * Hn;
        float acc = 0.f;
#pragma unroll 16
        for (int k = 0; k < Hn; k++) acc = fmaf(wrow[k], src[k], acc);
        acc += __shfl_xor_sync(0xffffffffu, acc, 1);
        if (half == 0) g_proj[bt * Hn + j] = fmaxf(acc + bp[j], 0.f);
    }
}

// ---------------- K5: logits GEMM  (M=1024, N=32000, K=128) ----------------
// 64x64 tile, 256 threads, 4x4 micro-tile, K staged in 2 chunks of 64.
// Tiles stored K-major in smem (padded to 68 floats: 16B-aligned, low conflict).
#define BM 64
#define BN 64
#define LDA 68
__global__ void k_logits(const float* __restrict__ Wfc,
                         const float* __restrict__ bfc,
                         float* __restrict__ logits) {
    __shared__ float a_s[64][LDA];
    __shared__ float b_s[64][LDA];
    int tid = threadIdx.x;
    int tx = tid & 15, ty = tid >> 4;
    int m0 = blockIdx.y * BM, n0 = blockIdx.x * BN;
    float acc[4][4];
#pragma unroll
    for (int i = 0; i < 4; i++)
#pragma unroll
        for (int j = 0; j < 4; j++) acc[i][j] = 0.f;

    for (int kc = 0; kc < 2; kc++) {
        for (int idx = tid; idx < 64 * 64; idx += 256) {
            int r = idx >> 6, k = idx & 63;
            a_s[k][r] = g_proj[(m0 + r) * Hn + kc * 64 + k];
            b_s[k][r] = Wfc[(size_t)(n0 + r) * Hn + kc * 64 + k];
        }
        __syncthreads();
#pragma unroll 8
        for (int k = 0; k < 64; k++) {
            float4 av = *(const float4*)&a_s[k][ty * 4];
            float4 bv = *(const float4*)&b_s[k][tx * 4];
            float a[4] = {av.x, av.y, av.z, av.w};
            float bb[4] = {bv.x, bv.y, bv.z, bv.w};
#pragma unroll
            for (int i = 0; i < 4; i++)
#pragma unroll
                for (int j = 0; j < 4; j++)
                    acc[i][j] = fmaf(a[i], bb[j], acc[i][j]);
        }
        __syncthreads();
    }
    float4 bf = *(const float4*)&bfc[n0 + tx * 4];
#pragma unroll
    for (int i = 0; i < 4; i++) {
        float4 o;
        o.x = acc[i][0] + bf.x;
        o.y = acc[i][1] + bf.y;
        o.z = acc[i][2] + bf.z;
        o.w = acc[i][3] + bf.w;
        *(float4*)&logits[(size_t)(m0 + ty * 4 + i) * Vn + n0 + tx * 4] = o;
    }
}

// ---------------- launch ----------------
extern "C" void kernel_launch(void* const* d_in, const int* in_sizes, int n_in,
                              void* d_out, int out_size) {
    const void* x = d_in[0];
    const float* hidden = (const float*)d_in[1];
    const float* etab = (const float*)d_in[2];
    const float* W_ih = (const float*)d_in[3];
    const float* W_hh = (const float*)d_in[4];
    const float* b_ih = (const float*)d_in[5];
    const float* b_hh = (const float*)d_in[6];
    const float* W1 = (const float*)d_in[7];
    const float* W2 = (const float*)d_in[8];
    const float* v = (const float*)d_in[9];
    const float* Wp = (const float*)d_in[10];
    const float* bp = (const float*)d_in[11];
    const float* Wfc = (const float*)d_in[12];
    const float* bfc = (const float*)d_in[13];

    float* out = (float*)d_out;
    float* out_logits = out;                                  // (B,T,V)
    float* out_hidden = out + (size_t)Bn * Tn * Vn;           // (1,B,H)
    float* out_weights = out_hidden + Bn * Hn;                // (B,T,T)

    k_detect<<<1, 256>>>((const unsigned*)x);
    k_embed<<<Bn * Tn, 128>>>(x, etab, W_ih, b_ih, b_hh);
    k_rnn<<<Bn, 256>>>(hidden, W_hh, out_hidden);
    k_qk<<<Bn * Tn, 256>>>(W1, W2);
    k_attn<<<Bn * Tn, 256>>>(v, Wp, bp, out_weights);
    k_logits<<<dim3(Vn / BN, (Bn * Tn) / BM), 256>>>(Wfc, bfc, out_logits);
}

// round 4
// speedup vs baseline: 1.2005x; 1.2005x over previous
#include <cuda_runtime.h>

#define Tn 512
#define Bn 2
#define Hn 128
#define En 32
#define Vn 32000

// ---------------- scratch (no allocations allowed) ----------------
__device__ float g_xp[Bn * Tn * Hn];    // input projections + biases
__device__ float g_rnn[Bn * Tn * Hn];   // RNN outputs
__device__ float g_q[Bn * Tn * Hn];     // query = rnn @ W1^T
__device__ float g_k[Bn * Tn * Hn];     // keys  = rnn @ W2^T
__device__ float g_proj[Bn * Tn * Hn];  // relu([rnn,ctx] @ Wp^T + bp)
__device__ int g_is64;                  // x element width flag

// ---------------- f32x2 packed-FMA helpers (SASS FFMA2, PTX-only) ----------------
#define FMA_F32X2(d, a, b, c) \
    asm("fma.rn.f32x2 %0, %1, %2, %3;" : "=l"(d) : "l"(a), "l"(b), "l"(c))
#define PACK_DUP_F32X2(d, x) \
    asm("mov.b64 %0, {%1, %1};" : "=l"(d) : "f"(x))
__device__ __forceinline__ float f2sum(unsigned long long p) {
    float lo, hi;
    asm("mov.b64 {%0, %1}, %2;" : "=f"(lo), "=f"(hi) : "l"(p));
    return lo + hi;
}

// accurate fast tanh (~1e-6 rel err)
__device__ __forceinline__ float fast_tanh(float x) {
    x = fminf(fmaxf(x, -15.f), 15.f);
    float e = __expf(2.f * x);
    return __fdividef(e - 1.f, e + 1.f);
}

// ---------------- K0: detect int64 vs int32 token layout ----------------
__global__ void k_detect(const unsigned* __restrict__ xw) {
    __shared__ int nz;
    if (threadIdx.x == 0) nz = 0;
    __syncthreads();
    for (int i = threadIdx.x; i < 512; i += blockDim.x)
        if (xw[2 * i + 1]) atomicOr(&nz, 1);
    __syncthreads();
    if (threadIdx.x == 0) g_is64 = (nz == 0);
}

// ---------------- K1: embedding + input projection ----------------
__global__ void k_embed(const void* __restrict__ xraw,
                        const float* __restrict__ etab,
                        const float* __restrict__ W_ih,
                        const float* __restrict__ b_ih,
                        const float* __restrict__ b_hh) {
    int bt = blockIdx.x;
    int h = threadIdx.x;
    __shared__ float emb[En];
    __shared__ int sidx;
    if (threadIdx.x == 0) {
        long long idx;
        if (g_is64) idx = ((const long long*)xraw)[bt];
        else        idx = (long long)(((const int*)xraw)[bt]);
        sidx = (int)idx;
    }
    __syncthreads();
    if (h < En) emb[h] = etab[(long long)sidx * En + h];
    __syncthreads();
    float acc = b_ih[h] + b_hh[h];
#pragma unroll
    for (int e = 0; e < En; e++) acc = fmaf(emb[e], W_ih[h * En + e], acc);
    g_xp[bt * Hn + h] = acc;
}

// ---------------- K2: sequential tanh-RNN scan (f32x2 packed) ----------------
// 128 threads, one per output j; full K=128 as 64 packed pairs in registers.
// (R2 bug: loop covered only half of K. Fixed: q < 32 covers all 32 ulonglong2.)
__global__ void __launch_bounds__(128, 1) k_rnn(const float* __restrict__ hidden,
                                                const float* __restrict__ W_hh,
                                                float* __restrict__ out_hidden) {
    int b = blockIdx.x;
    int j = threadIdx.x;
    // packed weights: w2[q] = (W_hh[j][2q], W_hh[j][2q+1])
    unsigned long long w2[64];
    const unsigned long long* wrow = (const unsigned long long*)(W_hh + j * Hn);
#pragma unroll
    for (int q = 0; q < 64; q++) w2[q] = wrow[q];

    __shared__ __align__(16) float hbuf[2][Hn];
    hbuf[0][j] = hidden[b * Hn + j];
    __syncthreads();

    const float* xp = g_xp + b * Tn * Hn;
    float* rnn = g_rnn + b * Tn * Hn;
    for (int t = 0; t < Tn; t++) {
        float xv = xp[t * Hn + j];
        const ulonglong2* h2 = (const ulonglong2*)hbuf[t & 1];
        unsigned long long a0 = 0ull, a1 = 0ull, a2 = 0ull, a3 = 0ull;
#pragma unroll
        for (int q = 0; q < 32; q += 2) {   // 32 ulonglong2 = 128 floats (full K)
            ulonglong2 hv0 = h2[q];
            ulonglong2 hv1 = h2[q + 1];
            FMA_F32X2(a0, w2[2 * q + 0], hv0.x, a0);
            FMA_F32X2(a1, w2[2 * q + 1], hv0.y, a1);
            FMA_F32X2(a2, w2[2 * q + 2], hv1.x, a2);
            FMA_F32X2(a3, w2[2 * q + 3], hv1.y, a3);
        }
        float s = (f2sum(a0) + f2sum(a1)) + (f2sum(a2) + f2sum(a3)) + xv;
        float hn = fast_tanh(s);
        hbuf[(t + 1) & 1][j] = hn;
        rnn[t * Hn + j] = hn;
        __syncthreads();
    }
    out_hidden[b * Hn + j] = hbuf[0][j];  // Tn even -> final state in buffer 0
}

// ---------------- K3: q/k projections as a tiled GEMM ----------------
// C[1024 x 256] = rnn @ [W1; W2]^T.  64x64 tiles, coalesced k-contiguous loads.
__global__ void __launch_bounds__(256) k_qk(const float* __restrict__ W1,
                                            const float* __restrict__ W2) {
    __shared__ float a_s[64][68];
    __shared__ float b_s[64][68];
    int tid = threadIdx.x;
    int tx = tid & 15, ty = tid >> 4;
    int n0 = blockIdx.x * 64, m0 = blockIdx.y * 64;
    const float* W = (n0 < Hn) ? W1 : W2;
    int nb = n0 & (Hn - 1);
    float acc[4][4];
#pragma unroll
    for (int i = 0; i < 4; i++)
#pragma unroll
        for (int jj = 0; jj < 4; jj++) acc[i][jj] = 0.f;

    for (int kc = 0; kc < 2; kc++) {
        for (int idx = tid; idx < 64 * 64; idx += 256) {
            int r = idx >> 6, k = idx & 63;
            a_s[k][r] = g_rnn[(m0 + r) * Hn + kc * 64 + k];
            b_s[k][r] = W[(nb + r) * Hn + kc * 64 + k];
        }
        __syncthreads();
#pragma unroll 8
        for (int k = 0; k < 64; k++) {
            float4 av = *(const float4*)&a_s[k][ty * 4];
            float4 bv = *(const float4*)&b_s[k][tx * 4];
            float a[4] = {av.x, av.y, av.z, av.w};
            float bb[4] = {bv.x, bv.y, bv.z, bv.w};
#pragma unroll
            for (int i = 0; i < 4; i++)
#pragma unroll
                for (int jj = 0; jj < 4; jj++)
                    acc[i][jj] = fmaf(a[i], bb[jj], acc[i][jj]);
        }
        __syncthreads();
    }
    float* dst = (n0 < Hn) ? g_q : g_k;
#pragma unroll
    for (int i = 0; i < 4; i++) {
        float4 o = {acc[i][0], acc[i][1], acc[i][2], acc[i][3]};
        *(float4*)&dst[(m0 + ty * 4 + i) * Hn + nb + tx * 4] = o;
    }
}

// ---------------- K4: additive attention + softmax + context + Wp proj ----------------
__global__ void __launch_bounds__(256) k_attn(const float* __restrict__ v,
                                              const float* __restrict__ Wp,
                                              const float* __restrict__ bp,
                                              float* __restrict__ out_w) {
    int bt = blockIdx.x;
    int b = bt >> 9, t = bt & 511;
    int tid = threadIdx.x;
    __shared__ float q_s[Hn], v_s[Hn], r_s[Hn], ctx_s[Hn];
    __shared__ float sc[Tn];
    __shared__ float red[256];
    if (tid < Hn) {
        q_s[tid] = g_q[bt * Hn + tid];
        v_s[tid] = v[tid];
        r_s[tid] = g_rnn[bt * Hn + tid];
    }
    __syncthreads();

    // scores[s] = sum_h tanh(q[t,h] + k[s,h]) * v[h],  s <= t
    int warp = tid >> 5, lane = tid & 31;
    for (int s = warp; s <= t; s += 8) {
        const float* krow = g_k + (b * Tn + s) * Hn;
        float p = 0.f;
#pragma unroll
        for (int i = 0; i < 4; i++) {
            int h = i * 32 + lane;
            p = fmaf(fast_tanh(q_s[h] + krow[h]), v_s[h], p);
        }
#pragma unroll
        for (int off = 16; off; off >>= 1) p += __shfl_xor_sync(0xffffffffu, p, off);
        if (lane == 0) sc[s] = p;
    }
    __syncthreads();

    // softmax over [0, t]
    float m = -1e30f;
    for (int s = tid; s <= t; s += 256) m = fmaxf(m, sc[s]);
    red[tid] = m;
    __syncthreads();
    for (int st = 128; st; st >>= 1) {
        if (tid < st) red[tid] = fmaxf(red[tid], red[tid + st]);
        __syncthreads();
    }
    float mx = red[0];
    __syncthreads();
    float ssum = 0.f;
    for (int s = tid; s <= t; s += 256) {
        float e = __expf(sc[s] - mx);
        sc[s] = e;
        ssum += e;
    }
    red[tid] = ssum;
    __syncthreads();
    for (int st = 128; st; st >>= 1) {
        if (tid < st) red[tid] += red[tid + st];
        __syncthreads();
    }
    float rinv = __fdividef(1.f, red[0]);
    __syncthreads();
    for (int s = tid; s < Tn; s += 256) {
        float wv = (s <= t) ? sc[s] * rinv : 0.f;
        out_w[(size_t)bt * Tn + s] = wv;
        if (s <= t) sc[s] = wv;
    }
    __syncthreads();

    // context[h] = sum_s w[s] * rnn[b,s,h]
    {
        int h = tid & 127, part = tid >> 7;
        float c = 0.f;
        for (int s = part; s <= t; s += 2)
            c = fmaf(sc[s], g_rnn[(b * Tn + s) * Hn + h], c);
        red[tid] = c;
        __syncthreads();
        if (tid < Hn) ctx_s[tid] = red[tid] + red[tid + 128];
        __syncthreads();
    }

    // proj: relu([rnn, ctx] @ Wp^T + bp)
    {
        int j = tid >> 1, half = tid & 1;
        const float* src = half ? ctx_s : r_s;
        const float* wrow = Wp + j * (2 * Hn) + half * Hn;
        float acc = 0.f;
#pragma unroll 16
        for (int k = 0; k < Hn; k++) acc = fmaf(wrow[k], src[k], acc);
        acc += __shfl_xor_sync(0xffffffffu, acc, 1);
        if (half == 0) g_proj[bt * Hn + j] = fmaxf(acc + bp[j], 0.f);
    }
}

// ---------------- K5: logits GEMM with packed f32x2 FMA ----------------
// M=1024, N=32000, K=128. 64x128 block tile, 256 threads, 4x8 micro-tile,
// K staged in 4 chunks of 32 (smem 25.6 KB -> good occupancy).
#define BM 64
#define BN 128
#define TK 32
#define LDA 68
#define LDB 132
__global__ void __launch_bounds__(256) k_logits(const float* __restrict__ Wfc,
                                                const float* __restrict__ bfc,
                                                float* __restrict__ logits) {
    __shared__ float a_s[TK][LDA];
    __shared__ float b_s[TK][LDB];
    int tid = threadIdx.x;
    int tx = tid & 15, ty = tid >> 4;
    int m0 = blockIdx.y * BM, n0 = blockIdx.x * BN;
    unsigned long long acc[4][4];  // 4 rows x 4 col-pairs (8 cols)
#pragma unroll
    for (int i = 0; i < 4; i++)
#pragma unroll
        for (int jj = 0; jj < 4; jj++) acc[i][jj] = 0ull;

    for (int kc = 0; kc < Hn / TK; kc++) {
        for (int idx = tid; idx < BM * TK; idx += 256) {
            int r = idx >> 5, k = idx & 31;
            a_s[k][r] = g_proj[(m0 + r) * Hn + kc * TK + k];
        }
        for (int idx = tid; idx < BN * TK; idx += 256) {
            int n = idx >> 5, k = idx & 31;
            b_s[k][n] = Wfc[(size_t)(n0 + n) * Hn + kc * TK + k];
        }
        __syncthreads();
#pragma unroll 8
        for (int k = 0; k < TK; k++) {
            float4 av = *(const float4*)&a_s[k][ty * 4];
            ulonglong2 bv0 = *(const ulonglong2*)&b_s[k][tx * 8];
            ulonglong2 bv1 = *(const ulonglong2*)&b_s[k][tx * 8 + 4];
            unsigned long long aa[4];
            PACK_DUP_F32X2(aa[0], av.x);
            PACK_DUP_F32X2(aa[1], av.y);
            PACK_DUP_F32X2(aa[2], av.z);
            PACK_DUP_F32X2(aa[3], av.w);
#pragma unroll
            for (int i = 0; i < 4; i++) {
                FMA_F32X2(acc[i][0], aa[i], bv0.x, acc[i][0]);
                FMA_F32X2(acc[i][1], aa[i], bv0.y, acc[i][1]);
                FMA_F32X2(acc[i][2], aa[i], bv1.x, acc[i][2]);
                FMA_F32X2(acc[i][3], aa[i], bv1.y, acc[i][3]);
            }
        }
        __syncthreads();
    }

    // epilogue: unpack pairs, add bias, store 8 floats per row
    float4 bfa = *(const float4*)&bfc[n0 + tx * 8];
    float4 bfb = *(const float4*)&bfc[n0 + tx * 8 + 4];
#pragma unroll
    for (int i = 0; i < 4; i++) {
        float c0, c1, c2, c3, c4, c5, c6, c7;
        asm("mov.b64 {%0, %1}, %2;" : "=f"(c0), "=f"(c1) : "l"(acc[i][0]));
        asm("mov.b64 {%0, %1}, %2;" : "=f"(c2), "=f"(c3) : "l"(acc[i][1]));
        asm("mov.b64 {%0, %1}, %2;" : "=f"(c4), "=f"(c5) : "l"(acc[i][2]));
        asm("mov.b64 {%0, %1}, %2;" : "=f"(c6), "=f"(c7) : "l"(acc[i][3]));
        float4 o0 = {c0 + bfa.x, c1 + bfa.y, c2 + bfa.z, c3 + bfa.w};
        float4 o1 = {c4 + bfb.x, c5 + bfb.y, c6 + bfb.z, c7 + bfb.w};
        size_t base = (size_t)(m0 + ty * 4 + i) * Vn + n0 + tx * 8;
        *(float4*)&logits[base] = o0;
        *(float4*)&logits[base + 4] = o1;
    }
}

// ---------------- launch ----------------
extern "C" void kernel_launch(void* const* d_in, const int* in_sizes, int n_in,
                              void* d_out, int out_size) {
    const void* x = d_in[0];
    const float* hidden = (const float*)d_in[1];
    const float* etab = (const float*)d_in[2];
    const float* W_ih = (const float*)d_in[3];
    const float* W_hh = (const float*)d_in[4];
    const float* b_ih = (const float*)d_in[5];
    const float* b_hh = (const float*)d_in[6];
    const float* W1 = (const float*)d_in[7];
    const float* W2 = (const float*)d_in[8];
    const float* v = (const float*)d_in[9];
    const float* Wp = (const float*)d_in[10];
    const float* bp = (const float*)d_in[11];
    const float* Wfc = (const float*)d_in[12];
    const float* bfc = (const float*)d_in[13];

    float* out = (float*)d_out;
    float* out_logits = out;                         // (B,T,V)
    float* out_hidden = out + (size_t)Bn * Tn * Vn;  // (1,B,H)
    float* out_weights = out_hidden + Bn * Hn;       // (B,T,T)

    k_detect<<<1, 256>>>((const unsigned*)x);
    k_embed<<<Bn * Tn, 128>>>(x, etab, W_ih, b_ih, b_hh);
    k_rnn<<<Bn, 128>>>(hidden, W_hh, out_hidden);
    k_qk<<<dim3(4, 16), 256>>>(W1, W2);
    k_attn<<<Bn * Tn, 256>>>(v, Wp, bp, out_weights);
    k_logits<<<dim3(Vn / BN, (Bn * Tn) / BM), 256>>>(Wfc, bfc, out_logits);
}

// round 6
// speedup vs baseline: 1.2384x; 1.0315x over previous
#include <cuda_runtime.h>

#define Tn 512
#define Bn 2
#define Hn 128
#define En 32
#define Vn 32000

// ---------------- scratch (no allocations allowed) ----------------
__device__ float g_xp[Bn * Tn * Hn];    // input projections + biases
__device__ float g_rnn[Bn * Tn * Hn];   // RNN outputs
__device__ float g_q[Bn * Tn * Hn];     // query = rnn @ W1^T
__device__ float g_k[Bn * Tn * Hn];     // keys  = rnn @ W2^T
__device__ float g_proj[Bn * Tn * Hn];  // relu([rnn,ctx] @ Wp^T + bp)

// ---------------- f32x2 packed-FMA helpers (SASS FFMA2, PTX-only) ----------------
#define FMA_F32X2(d, a, b, c) \
    asm("fma.rn.f32x2 %0, %1, %2, %3;" : "=l"(d) : "l"(a), "l"(b), "l"(c))
#define PACK_DUP_F32X2(d, x) \
    asm("mov.b64 %0, {%1, %1};" : "=l"(d) : "f"(x))
__device__ __forceinline__ float f2sum(unsigned long long p) {
    float lo, hi;
    asm("mov.b64 {%0, %1}, %2;" : "=f"(lo), "=f"(hi) : "l"(p));
    return lo + hi;
}

// accurate MUFU tanh (~1e-6 rel err): rare-fallback path only
__device__ __forceinline__ float fast_tanh(float x) {
    x = fminf(fmaxf(x, -15.f), 15.f);
    float e = __expf(2.f * x);
    return __fdividef(e - 1.f, e + 1.f);
}

// Taylor tanh on FMA pipe: abs err <= 1.2e-5 for |x| <= 0.55
#define TANH_C1 (-0.33333333f)
#define TANH_C2 (0.13333334f)
#define TANH_C3 (-0.05396825f)
#define TANH_C4 (0.02186949f)
__device__ __forceinline__ float poly_tanh(float x) {
    float u = x * x;
    float p = fmaf(u, TANH_C4, TANH_C3);
    p = fmaf(u, p, TANH_C2);
    p = fmaf(u, p, TANH_C1);
    p = fmaf(u, p, 1.0f);
    return x * p;
}

// ---------------- K1: embedding + input projection (detect folded in) ----------------
__global__ void k_embed(const unsigned* __restrict__ xw,
                        const float* __restrict__ etab,
                        const float* __restrict__ W_ih,
                        const float* __restrict__ b_ih,
                        const float* __restrict__ b_hh) {
    int bt = blockIdx.x;
    int h = threadIdx.x;
    // layout detection: int64 tokens -> all high words (2i+1) zero.
    // Every block scans ALL 512 high-words (deterministic, L2-resident).
    int nz = 0;
    for (int i = threadIdx.x; i < 512; i += 128)
        nz |= (xw[2 * i + 1] != 0u);
    int is32 = __syncthreads_or(nz);

    __shared__ float emb[En];
    __shared__ int sidx;
    if (threadIdx.x == 0) {
        long long idx;
        if (is32) idx = (long long)(((const int*)xw)[bt]);
        else      idx = ((const long long*)xw)[bt];
        sidx = (int)idx;
    }
    __syncthreads();
    if (h < En) emb[h] = etab[(long long)sidx * En + h];
    __syncthreads();
    float acc = b_ih[h] + b_hh[h];
#pragma unroll
    for (int e = 0; e < En; e++) acc = fmaf(emb[e], W_ih[h * En + e], acc);
    g_xp[bt * Hn + h] = acc;
}

// ---------------- K2: sequential tanh-RNN scan (f32x2 + poly tanh) ----------------
// 128 threads, one per output j; full K=128 as 64 packed pairs in registers.
__global__ void __launch_bounds__(128, 1) k_rnn(const float* __restrict__ hidden,
                                                const float* __restrict__ W_hh,
                                                float* __restrict__ out_hidden) {
    int b = blockIdx.x;
    int j = threadIdx.x;
    unsigned long long w2[64];  // w2[q] = (W_hh[j][2q], W_hh[j][2q+1])
    const unsigned long long* wrow = (const unsigned long long*)(W_hh + j * Hn);
#pragma unroll
    for (int q = 0; q < 64; q++) w2[q] = wrow[q];

    __shared__ __align__(16) float hbuf[2][Hn];
    hbuf[0][j] = hidden[b * Hn + j];
    __syncthreads();

    const float* xp = g_xp + b * Tn * Hn;
    float* rnn = g_rnn + b * Tn * Hn;
    float xv_next = xp[j];  // prefetch t=0
    for (int t = 0; t < Tn; t++) {
        float xv = xv_next;
        if (t + 1 < Tn) xv_next = xp[(t + 1) * Hn + j];  // hide LDG behind compute
        const ulonglong2* h2 = (const ulonglong2*)hbuf[t & 1];
        unsigned long long a0 = 0ull, a1 = 0ull, a2 = 0ull, a3 = 0ull;
#pragma unroll
        for (int q = 0; q < 32; q += 2) {  // 32 ulonglong2 = 128 floats (full K)
            ulonglong2 hv0 = h2[q];
            ulonglong2 hv1 = h2[q + 1];
            FMA_F32X2(a0, w2[2 * q + 0], hv0.x, a0);
            FMA_F32X2(a1, w2[2 * q + 1], hv0.y, a1);
            FMA_F32X2(a2, w2[2 * q + 2], hv1.x, a2);
            FMA_F32X2(a3, w2[2 * q + 3], hv1.y, a3);
        }
        float s = (f2sum(a0) + f2sum(a1)) + (f2sum(a2) + f2sum(a3)) + xv;
        float hn = poly_tanh(s);
        // warp-uniform rare fallback: keeps MUFU off the hot path entirely
        if (__any_sync(0xffffffffu, fabsf(s) > 0.55f)) hn = fast_tanh(s);
        hbuf[(t + 1) & 1][j] = hn;
        rnn[t * Hn + j] = hn;
        __syncthreads();
    }
    out_hidden[b * Hn + j] = hbuf[0][j];  // Tn even -> final state in buffer 0
}

// ---------------- K3: q/k projections, 32x32 tiles (256 blocks) ----------------
__global__ void __launch_bounds__(128) k_qk(const float* __restrict__ W1,
                                            const float* __restrict__ W2) {
    __shared__ float a_s[128][34];  // [k][m], pad 34: float2 loads 8B-aligned
    __shared__ float b_s[128][36];  // [k][n], pad 36: float4 loads 16B-aligned
    int tid = threadIdx.x;
    int tx = tid & 7, ty = tid >> 3;  // tx: 8 n-quads, ty: 16 m-pairs
    int n0 = blockIdx.x * 32, m0 = blockIdx.y * 32;
    const float* W = (n0 < Hn) ? W1 : W2;
    int nb = n0 & (Hn - 1);

    for (int idx = tid; idx < 32 * 128; idx += 128) {
        int r = idx >> 7, k = idx & 127;
        a_s[k][r] = g_rnn[(m0 + r) * Hn + k];
        b_s[k][r] = W[(nb + r) * Hn + k];
    }
    __syncthreads();

    float acc[2][4];
#pragma unroll
    for (int i = 0; i < 2; i++)
#pragma unroll
        for (int jj = 0; jj < 4; jj++) acc[i][jj] = 0.f;
#pragma unroll 4
    for (int k = 0; k < 128; k++) {
        float2 av = *(const float2*)&a_s[k][ty * 2];
        float4 bv = *(const float4*)&b_s[k][tx * 4];
        acc[0][0] = fmaf(av.x, bv.x, acc[0][0]);
        acc[0][1] = fmaf(av.x, bv.y, acc[0][1]);
        acc[0][2] = fmaf(av.x, bv.z, acc[0][2]);
        acc[0][3] = fmaf(av.x, bv.w, acc[0][3]);
        acc[1][0] = fmaf(av.y, bv.x, acc[1][0]);
        acc[1][1] = fmaf(av.y, bv.y, acc[1][1]);
        acc[1][2] = fmaf(av.y, bv.z, acc[1][2]);
        acc[1][3] = fmaf(av.y, bv.w, acc[1][3]);
    }
    float* dst = (n0 < Hn) ? g_q : g_k;
#pragma unroll
    for (int i = 0; i < 2; i++) {
        float4 o = {acc[i][0], acc[i][1], acc[i][2], acc[i][3]};
        *(float4*)&dst[(m0 + ty * 2 + i) * Hn + nb + tx * 4] = o;
    }
}

// ---------------- K4: additive attention + softmax + context + Wp proj ----------------
__global__ void __launch_bounds__(256) k_attn(const float* __restrict__ v,
                                              const float* __restrict__ Wp,
                                              const float* __restrict__ bp,
                                              float* __restrict__ out_w) {
    int bt = blockIdx.x;
    int b = bt >> 9, t = bt & 511;
    int tid = threadIdx.x;
    __shared__ float q_s[Hn], v_s[Hn], r_s[Hn], ctx_s[Hn];
    __shared__ float sc[Tn];
    __shared__ float red[256];
    if (tid < Hn) {
        q_s[tid] = g_q[bt * Hn + tid];
        v_s[tid] = v[tid];
        r_s[tid] = g_rnn[bt * Hn + tid];
    }
    __syncthreads();

    // scores[s] = sum_h tanh(q[t,h] + k[s,h]) * v[h],  s <= t  — poly tanh on FMA pipe
    int warp = tid >> 5, lane = tid & 31;
    for (int s = warp; s <= t; s += 8) {
        const float* krow = g_k + (b * Tn + s) * Hn;
        float xa[4], ya[4];
        float mabs = 0.f;
#pragma unroll
        for (int i = 0; i < 4; i++) {
            int h = i * 32 + lane;
            xa[i] = q_s[h] + krow[h];
            mabs = fmaxf(mabs, fabsf(xa[i]));
        }
#pragma unroll
        for (int i = 0; i < 4; i++) ya[i] = poly_tanh(xa[i]);
        if (__any_sync(0xffffffffu, mabs > 0.55f)) {  // warp-uniform rare fallback
#pragma unroll
            for (int i = 0; i < 4; i++) ya[i] = fast_tanh(xa[i]);
        }
        float p = 0.f;
#pragma unroll
        for (int i = 0; i < 4; i++) p = fmaf(ya[i], v_s[i * 32 + lane], p);
#pragma unroll
        for (int off = 16; off; off >>= 1) p += __shfl_xor_sync(0xffffffffu, p, off);
        if (lane == 0) sc[s] = p;
    }
    __syncthreads();

    // softmax over [0, t]
    float m = -1e30f;
    for (int s = tid; s <= t; s += 256) m = fmaxf(m, sc[s]);
    red[tid] = m;
    __syncthreads();
    for (int st = 128; st; st >>= 1) {
        if (tid < st) red[tid] = fmaxf(red[tid], red[tid + st]);
        __syncthreads();
    }
    float mx = red[0];
    __syncthreads();
    float ssum = 0.f;
    for (int s = tid; s <= t; s += 256) {
        float e = __expf(sc[s] - mx);
        sc[s] = e;
        ssum += e;
    }
    red[tid] = ssum;
    __syncthreads();
    for (int st = 128; st; st >>= 1) {
        if (tid < st) red[tid] += red[tid + st];
        __syncthreads();
    }
    float rinv = __fdividef(1.f, red[0]);
    __syncthreads();
    for (int s = tid; s < Tn; s += 256) {
        float wv = (s <= t) ? sc[s] * rinv : 0.f;
        out_w[(size_t)bt * Tn + s] = wv;
        if (s <= t) sc[s] = wv;
    }
    __syncthreads();

    // context[h] = sum_s w[s] * rnn[b,s,h]
    {
        int h = tid & 127, part = tid >> 7;
        float c = 0.f;
        for (int s = part; s <= t; s += 2)
            c = fmaf(sc[s], g_rnn[(b * Tn + s) * Hn + h], c);
        red[tid] = c;
        __syncthreads();
        if (tid < Hn) ctx_s[tid] = red[tid] + red[tid + 128];
        __syncthreads();
    }

    // proj: relu([rnn, ctx] @ Wp^T + bp)
    {
        int j = tid >> 1, half = tid & 1;
        const float* src = half ? ctx_s : r_s;
        const float* wrow = Wp + j * (2 * Hn) + half * Hn;
        float acc = 0.f;
#pragma unroll 16
        for (int k = 0; k < Hn; k++) acc = fmaf(wrow[k], src[k], acc);
        acc += __shfl_xor_sync(0xffffffffu, acc, 1);
        if (half == 0) g_proj[bt * Hn + j] = fmaxf(acc + bp[j], 0.f);
    }
}

// ---------------- K5: logits GEMM with packed f32x2 FMA ----------------
#define BM 64
#define BN 128
#define TK 32
#define LDA 68
#define LDB 132
__global__ void __launch_bounds__(256) k_logits(const float* __restrict__ Wfc,
                                                const float* __restrict__ bfc,
                                                float* __restrict__ logits) {
    __shared__ float a_s[TK][LDA];
    __shared__ float b_s[TK][LDB];
    int tid = threadIdx.x;
    int tx = tid & 15, ty = tid >> 4;
    int m0 = blockIdx.y * BM, n0 = blockIdx.x * BN;
    unsigned long long acc[4][4];
#pragma unroll
    for (int i = 0; i < 4; i++)
#pragma unroll
        for (int jj = 0; jj < 4; jj++) acc[i][jj] = 0ull;

    for (int kc = 0; kc < Hn / TK; kc++) {
        for (int idx = tid; idx < BM * TK; idx += 256) {
            int r = idx >> 5, k = idx & 31;
            a_s[k][r] = g_proj[(m0 + r) * Hn + kc * TK + k];
        }
        for (int idx = tid; idx < BN * TK; idx += 256) {
            int n = idx >> 5, k = idx & 31;
            b_s[k][n] = Wfc[(size_t)(n0 + n) * Hn + kc * TK + k];
        }
        __syncthreads();
#pragma unroll 8
        for (int k = 0; k < TK; k++) {
            float4 av = *(const float4*)&a_s[k][ty * 4];
            ulonglong2 bv0 = *(const ulonglong2*)&b_s[k][tx * 8];
            ulonglong2 bv1 = *(const ulonglong2*)&b_s[k][tx * 8 + 4];
            unsigned long long aa[4];
            PACK_DUP_F32X2(aa[0], av.x);
            PACK_DUP_F32X2(aa[1], av.y);
            PACK_DUP_F32X2(aa[2], av.z);
            PACK_DUP_F32X2(aa[3], av.w);
#pragma unroll
            for (int i = 0; i < 4; i++) {
                FMA_F32X2(acc[i][0], aa[i], bv0.x, acc[i][0]);
                FMA_F32X2(acc[i][1], aa[i], bv0.y, acc[i][1]);
                FMA_F32X2(acc[i][2], aa[i], bv1.x, acc[i][2]);
                FMA_F32X2(acc[i][3], aa[i], bv1.y, acc[i][3]);
            }
        }
        __syncthreads();
    }

    float4 bfa = *(const float4*)&bfc[n0 + tx * 8];
    float4 bfb = *(const float4*)&bfc[n0 + tx * 8 + 4];
#pragma unroll
    for (int i = 0; i < 4; i++) {
        float c0, c1, c2, c3, c4, c5, c6, c7;
        asm("mov.b64 {%0, %1}, %2;" : "=f"(c0), "=f"(c1) : "l"(acc[i][0]));
        asm("mov.b64 {%0, %1}, %2;" : "=f"(c2), "=f"(c3) : "l"(acc[i][1]));
        asm("mov.b64 {%0, %1}, %2;" : "=f"(c4), "=f"(c5) : "l"(acc[i][2]));
        asm("mov.b64 {%0, %1}, %2;" : "=f"(c6), "=f"(c7) : "l"(acc[i][3]));
        float4 o0 = {c0 + bfa.x, c1 + bfa.y, c2 + bfa.z, c3 + bfa.w};
        float4 o1 = {c4 + bfb.x, c5 + bfb.y, c6 + bfb.z, c7 + bfb.w};
        size_t base = (size_t)(m0 + ty * 4 + i) * Vn + n0 + tx * 8;
        *(float4*)&logits[base] = o0;
        *(float4*)&logits[base + 4] = o1;
    }
}

// ---------------- launch ----------------
extern "C" void kernel_launch(void* const* d_in, const int* in_sizes, int n_in,
                              void* d_out, int out_size) {
    const void* x = d_in[0];
    const float* hidden = (const float*)d_in[1];
    const float* etab = (const float*)d_in[2];
    const float* W_ih = (const float*)d_in[3];
    const float* W_hh = (const float*)d_in[4];
    const float* b_ih = (const float*)d_in[5];
    const float* b_hh = (const float*)d_in[6];
    const float* W1 = (const float*)d_in[7];
    const float* W2 = (const float*)d_in[8];
    const float* v = (const float*)d_in[9];
    const float* Wp = (const float*)d_in[10];
    const float* bp = (const float*)d_in[11];
    const float* Wfc = (const float*)d_in[12];
    const float* bfc = (const float*)d_in[13];

    float* out = (float*)d_out;
    float* out_logits = out;                         // (B,T,V)
    float* out_hidden = out + (size_t)Bn * Tn * Vn;  // (1,B,H)
    float* out_weights = out_hidden + Bn * Hn;       // (B,T,T)

    k_embed<<<Bn * Tn, 128>>>((const unsigned*)x, etab, W_ih, b_ih, b_hh);
    k_rnn<<<Bn, 128>>>(hidden, W_hh, out_hidden);
    k_qk<<<dim3(8, 32), 128>>>(W1, W2);
    k_attn<<<Bn * Tn, 256>>>(v, Wp, bp, out_weights);
    k_logits<<<dim3(Vn / BN, (Bn * Tn) / BM), 256>>>(Wfc, bfc, out_logits);
}